// round 4
// baseline (speedup 1.0000x reference)
#include <cuda_runtime.h>
#include <cstdint>

#define B_TOT   4096
#define NTOK    49
#define CDIM    128
#define NHEAD   4
#define HDIM    32
#define TPB     256
#define NWARP   8
#define SCALE   0.17677669529663687f   /* 32^-0.5 */
#define FULLM   0xffffffffu
#define NEG_INF (__int_as_float(0xff800000))

// ---- packed f32x2 helpers (sm_100+ PTX) --------------------------------
static __device__ __forceinline__ void ffma2(unsigned long long& acc,
                                             unsigned long long a,
                                             unsigned long long b) {
    asm("fma.rn.f32x2 %0, %1, %2, %0;" : "+l"(acc) : "l"(a), "l"(b));
}
static __device__ __forceinline__ unsigned long long packf2(float x, float y) {
    unsigned long long r;
    asm("mov.b64 %0, {%1, %2};" : "=l"(r) : "f"(x), "f"(y));
    return r;
}
static __device__ __forceinline__ float2 unpackf2(unsigned long long v) {
    float2 r;
    asm("mov.b64 {%0, %1}, %2;" : "=f"(r.x), "=f"(r.y) : "l"(v));
    return r;
}

// ---- shared memory layout ----------------------------------------------
struct Smem {
    unsigned long long wsp[64 * 129];      // W chunk, k-paired+transposed: [k/2][col]
    float qs[NTOK * CDIM];                 // q (temperature-scaled), row-major
    float kt[CDIM * 57 + 64];              // k transposed: kt[col*57 + m], padded
    float vs[NTOK * CDIM];                 // v row-major
    float obuf[NTOK * CDIM];               // attention output, row-major
    int   ridx[NTOK * NTOK];
    float rtab[169 * 4];
    float bqs[3 * CDIM];                   // qkv bias
    float pbs[CDIM];                       // proj bias
    float invT[64];
    float uBs[64];
    float gts[NHEAD * NTOK];
};
#define SMEM_BYTES ((int)sizeof(Smem))

// stage a 128x128 weight block W[c][k] into wsp[(k/2)*129 + c] as (w[k],w[k+1])
static __device__ __forceinline__ void stage_w(Smem* sm, const float* __restrict__ src, int tid) {
    float* wf = reinterpret_cast<float*>(sm->wsp);
    #pragma unroll 4
    for (int idx = tid; idx < 128 * 128; idx += TPB) {
        int c = idx >> 7;
        int k = idx & 127;
        wf[(k >> 1) * 258 + (c << 1) + (k & 1)] = src[(c << 7) + k];  // conflict-free
    }
}

// 49x128 <- xr(regs) @ Wchunk : acc[rr][cc] packed over k-halves
static __device__ __forceinline__ void gemm_block(const Smem* sm,
                                                  const float (&xr)[7][4],
                                                  int lane,
                                                  unsigned long long (&acc)[7][4]) {
    #pragma unroll
    for (int rr = 0; rr < 7; rr++)
        #pragma unroll
        for (int cc = 0; cc < 4; cc++) acc[rr][cc] = 0ull;

    const unsigned long long* wq = sm->wsp;
    #pragma unroll 4
    for (int k2 = 0; k2 < 64; k2++) {
        unsigned long long wv0 = wq[k2 * 129 + lane];
        unsigned long long wv1 = wq[k2 * 129 + lane + 32];
        unsigned long long wv2 = wq[k2 * 129 + lane + 64];
        unsigned long long wv3 = wq[k2 * 129 + lane + 96];
        int kk = k2 >> 4;
        int l0 = (k2 << 1) & 31;
        #pragma unroll
        for (int rr = 0; rr < 7; rr++) {
            float xa = __shfl_sync(FULLM, xr[rr][kk], l0);
            float xb = __shfl_sync(FULLM, xr[rr][kk], l0 + 1);
            unsigned long long xp = packf2(xa, xb);
            ffma2(acc[rr][0], xp, wv0);
            ffma2(acc[rr][1], xp, wv1);
            ffma2(acc[rr][2], xp, wv2);
            ffma2(acc[rr][3], xp, wv3);
        }
    }
}

__global__ void __launch_bounds__(TPB, 1)
attn_win_kernel(const float* __restrict__ x,
                const float* __restrict__ ut,
                const float* __restrict__ ub,
                const float* __restrict__ gate,
                const float* __restrict__ qkv_w,
                const float* __restrict__ qkv_b,
                const float* __restrict__ proj_w,
                const float* __restrict__ proj_b,
                const float* __restrict__ rel_table,
                const int*   __restrict__ rel_index,
                float* __restrict__ out) {
    extern __shared__ char smem_raw[];
    Smem* sm = reinterpret_cast<Smem*>(smem_raw);

    const int b    = blockIdx.x;
    const int tid  = threadIdx.x;
    const int lane = tid & 31;
    const int wy   = tid >> 5;

    // ---------------- stage constants -------------------------------
    for (int i = tid; i < NTOK * NTOK; i += TPB) sm->ridx[i] = rel_index[i];
    for (int i = tid; i < 169 * 4; i += TPB)     sm->rtab[i] = rel_table[i];
    for (int i = tid; i < 3 * CDIM; i += TPB)    sm->bqs[i]  = qkv_b[i];
    if (tid < CDIM) sm->pbs[tid] = proj_b[tid];
    if (tid < NTOK) {
        float t  = ut[b * NTOK + tid];
        float sg = 1.f / (1.f + __expf(-t));
        sm->invT[tid] = 1.f / (0.1f + 4.f * sg);
        float u = ub[b * NTOK + tid];
        sm->uBs[tid] = u > 0.f ? u : 0.f;
    }
    if (tid < NHEAD * NTOK) sm->gts[tid] = gate[(size_t)b * (NHEAD * NTOK) + tid];
    stage_w(sm, qkv_w, tid);   // chunk 0 (q)

    // ---------------- preload x rows into registers ------------------
    const int R = (wy == 0) ? 7 : 6;        // rows n = wy + 8*rr, n<49
    float xreg[7][4];
    #pragma unroll
    for (int rr = 0; rr < 7; rr++) {
        int n = wy + 8 * rr;
        #pragma unroll
        for (int kk = 0; kk < 4; kk++)
            xreg[rr][kk] = (n < NTOK)
                ? x[(size_t)b * (NTOK * CDIM) + n * CDIM + kk * 32 + lane] : 0.f;
    }
    __syncthreads();

    // ---------------- qkv GEMM (3 chunks: q, k, v) -------------------
    unsigned long long acc[7][4];
    for (int j = 0; j < 3; j++) {
        gemm_block(sm, xreg, lane, acc);
        #pragma unroll
        for (int rr = 0; rr < 7; rr++) {
            if (rr < R) {
                int n = wy + 8 * rr;
                #pragma unroll
                for (int cc = 0; cc < 4; cc++) {
                    int c = lane + 32 * cc;
                    float2 s = unpackf2(acc[rr][cc]);
                    float v = s.x + s.y + sm->bqs[j * CDIM + c];
                    if (j == 0)      sm->qs[n * CDIM + c] = v * sm->invT[n];
                    else if (j == 1) sm->kt[c * 57 + n]   = v;
                    else             sm->vs[n * CDIM + c] = v;
                }
            }
        }
        __syncthreads();
        if (j < 2) { stage_w(sm, qkv_w + (j + 1) * 128 * 128, tid); __syncthreads(); }
    }
    // ws is free now: stage proj_w early (consumed only after next barrier)
    stage_w(sm, proj_w, tid);

    // ---------------- attention: 28 blocks of (head, 7 rows) ---------
    for (int bk = wy; bk < 28; bk += NWARP) {
        int h = bk / 7, g = bk % 7;
        int n0 = g * 7, hd0 = h * HDIM;

        float qreg[7];
        #pragma unroll
        for (int r = 0; r < 7; r++) qreg[r] = sm->qs[(n0 + r) * CDIM + hd0 + lane];

        float s0[7], s1[7];
        #pragma unroll
        for (int r = 0; r < 7; r++) { s0[r] = 0.f; s1[r] = 0.f; }

        #pragma unroll 8
        for (int d = 0; d < HDIM; d++) {
            float k0 = sm->kt[(hd0 + d) * 57 + lane];
            float k1 = sm->kt[(hd0 + d) * 57 + 32 + lane];
            #pragma unroll
            for (int r = 0; r < 7; r++) {
                float qv = __shfl_sync(FULLM, qreg[r], d);
                s0[r] = fmaf(qv, k0, s0[r]);
                s1[r] = fmaf(qv, k1, s1[r]);
            }
        }

        float uB0 = sm->uBs[lane];
        float uB1 = (lane < 17) ? sm->uBs[lane + 32] : 0.f;
        float p0[7], p1[7];
        #pragma unroll
        for (int r = 0; r < 7; r++) {
            int n = n0 + r;
            float bias0 = sm->rtab[sm->ridx[n * NTOK + lane] * 4 + h] - uB0;
            float a0 = fmaf(s0[r], SCALE, bias0);
            float a1 = NEG_INF;
            if (lane < 17) {
                float bias1 = sm->rtab[sm->ridx[n * NTOK + lane + 32] * 4 + h] - uB1;
                a1 = fmaf(s1[r], SCALE, bias1);
            }
            float mx = fmaxf(a0, a1);
            #pragma unroll
            for (int o = 16; o > 0; o >>= 1) mx = fmaxf(mx, __shfl_xor_sync(FULLM, mx, o));
            float e0 = __expf(a0 - mx);
            float e1 = (lane < 17) ? __expf(a1 - mx) : 0.f;
            float smv = e0 + e1;
            #pragma unroll
            for (int o = 16; o > 0; o >>= 1) smv += __shfl_xor_sync(FULLM, smv, o);
            float inv = __fdividef(1.f, smv);
            p0[r] = e0 * inv;
            p1[r] = e1 * inv;
        }

        float o_[7];
        #pragma unroll
        for (int r = 0; r < 7; r++) o_[r] = 0.f;
        #pragma unroll 8
        for (int m = 0; m < 32; m++) {
            float vv = sm->vs[m * CDIM + hd0 + lane];
            #pragma unroll
            for (int r = 0; r < 7; r++)
                o_[r] = fmaf(__shfl_sync(FULLM, p0[r], m), vv, o_[r]);
        }
        #pragma unroll 8
        for (int m = 0; m < 17; m++) {
            float vv = sm->vs[(m + 32) * CDIM + hd0 + lane];
            #pragma unroll
            for (int r = 0; r < 7; r++)
                o_[r] = fmaf(__shfl_sync(FULLM, p1[r], m), vv, o_[r]);
        }
        #pragma unroll
        for (int r = 0; r < 7; r++)
            sm->obuf[(n0 + r) * CDIM + hd0 + lane] = o_[r] * sm->gts[h * NTOK + n0 + r];
    }
    __syncthreads();

    // ---------------- output projection ------------------------------
    float oreg[7][4];
    #pragma unroll
    for (int rr = 0; rr < 7; rr++) {
        int n = wy + 8 * rr;
        #pragma unroll
        for (int kk = 0; kk < 4; kk++)
            oreg[rr][kk] = (n < NTOK) ? sm->obuf[n * CDIM + kk * 32 + lane] : 0.f;
    }
    gemm_block(sm, oreg, lane, acc);
    #pragma unroll
    for (int rr = 0; rr < 7; rr++) {
        if (rr < R) {
            int n = wy + 8 * rr;
            #pragma unroll
            for (int cc = 0; cc < 4; cc++) {
                int c = lane + 32 * cc;
                float2 s = unpackf2(acc[rr][cc]);
                out[(size_t)b * (NTOK * CDIM) + n * CDIM + c] = s.x + s.y + sm->pbs[c];
            }
        }
    }
}

extern "C" void kernel_launch(void* const* d_in, const int* in_sizes, int n_in,
                              void* d_out, int out_size) {
    const float* x      = (const float*)d_in[0];
    const float* ut     = (const float*)d_in[1];
    const float* ubias  = (const float*)d_in[2];
    const float* gate   = (const float*)d_in[3];
    const float* qkv_w  = (const float*)d_in[4];
    const float* qkv_b  = (const float*)d_in[5];
    const float* proj_w = (const float*)d_in[6];
    const float* proj_b = (const float*)d_in[7];
    const float* rtab   = (const float*)d_in[8];
    const int*   ridx   = (const int*)d_in[9];
    float* out = (float*)d_out;

    cudaFuncSetAttribute(attn_win_kernel,
                         cudaFuncAttributeMaxDynamicSharedMemorySize, SMEM_BYTES);
    attn_win_kernel<<<B_TOT, TPB, SMEM_BYTES>>>(
        x, ut, ubias, gate, qkv_w, qkv_b, proj_w, proj_b, rtab, ridx, out);
}

// round 6
// speedup vs baseline: 1.3296x; 1.3296x over previous
#include <cuda_runtime.h>
#include <cstdint>

#define B_TOT   4096
#define NTOK    49
#define CDIM    128
#define NHEAD   4
#define HDIM    32
#define TPB     512
#define SCALE   0.17677669529663687f   /* 32^-0.5 */
#define FULLM   0xffffffffu
#define NEG_INF (__int_as_float(0xff800000))

// ---- packed f32x2 helpers (sm_100+ PTX) --------------------------------
static __device__ __forceinline__ void ffma2(unsigned long long& acc,
                                             unsigned long long a,
                                             unsigned long long b) {
    asm("fma.rn.f32x2 %0, %1, %2, %0;" : "+l"(acc) : "l"(a), "l"(b));
}
static __device__ __forceinline__ float2 unpackf2(unsigned long long v) {
    float2 r;
    asm("mov.b64 {%0, %1}, %2;" : "=f"(r.x), "=f"(r.y) : "l"(v));
    return r;
}

// ---- shared memory layout ----------------------------------------------
// wsp: W chunk packed by k-quads: ulonglong2 wsp[k4][col], row pad 129
//      float view: wf[(k>>2)*516 + c*4 + (k&3)]
// xp : x (then gated attn output) packed: ulonglong2 xp[k4][n], row pad 51
//      float view: xpf[(k>>2)*204 + n*4 + (k&3)]
struct Smem {
    ulonglong2 wsp[32 * 129];              // 66.0 KB
    ulonglong2 xp[32 * 51];                // 26.1 KB
    float qs[NTOK * CDIM];                 // 25.1 KB  q (temp-scaled), row-major
    float kt[CDIM * 51 + 64];              // 26.4 KB  k transposed kt[c*51+m]
    float vs[NTOK * CDIM];                 // 25.1 KB  v row-major
    int   ridx[NTOK * NTOK];               //  9.6 KB
    float rtab[169 * 4];
    float bqs[3 * CDIM];
    float pbs[CDIM];
    float invT[64];
    float uBs[64];
    float gts[NHEAD * NTOK];
};
#define SMEM_BYTES ((int)sizeof(Smem))

// stage a 128x128 weight block W[c][k] into packed layout (conflict-free STS)
static __device__ __forceinline__ void stage_w(Smem* sm, const float* __restrict__ src, int tid) {
    float* wf = reinterpret_cast<float*>(sm->wsp);
    #pragma unroll 8
    for (int idx = tid; idx < 128 * 128; idx += TPB) {
        int c = idx >> 7;
        int k = idx & 127;
        wf[(k >> 2) * 516 + (c << 2) + (k & 3)] = src[idx];
    }
}

// 3-or-4 rows x 128 cols GEMM: acc[rr][cc] packed (lo = even k, hi = odd k)
template <int NR>
static __device__ __forceinline__ void gemm_block(const Smem* sm, const int* nrow,
                                                  int lane, unsigned long long (&acc)[4][4]) {
    #pragma unroll
    for (int rr = 0; rr < 4; rr++)
        #pragma unroll
        for (int cc = 0; cc < 4; cc++) acc[rr][cc] = 0ull;

    const ulonglong2* wq = sm->wsp;
    const ulonglong2* xq = sm->xp;
    #pragma unroll 2
    for (int k4 = 0; k4 < 32; k4++) {
        ulonglong2 w0 = wq[k4 * 129 + lane];
        ulonglong2 w1 = wq[k4 * 129 + lane + 32];
        ulonglong2 w2 = wq[k4 * 129 + lane + 64];
        ulonglong2 w3 = wq[k4 * 129 + lane + 96];
        ulonglong2 xv[NR];
        #pragma unroll
        for (int rr = 0; rr < NR; rr++) xv[rr] = xq[k4 * 51 + nrow[rr]];  // broadcast
        #pragma unroll
        for (int rr = 0; rr < NR; rr++) {
            ffma2(acc[rr][0], xv[rr].x, w0.x);
            ffma2(acc[rr][1], xv[rr].x, w1.x);
            ffma2(acc[rr][2], xv[rr].x, w2.x);
            ffma2(acc[rr][3], xv[rr].x, w3.x);
        }
        #pragma unroll
        for (int rr = 0; rr < NR; rr++) {
            ffma2(acc[rr][0], xv[rr].y, w0.y);
            ffma2(acc[rr][1], xv[rr].y, w1.y);
            ffma2(acc[rr][2], xv[rr].y, w2.y);
            ffma2(acc[rr][3], xv[rr].y, w3.y);
        }
    }
}

// attention for one (head, row-group) block; R rows, warp lanes = keys / dims
template <int R>
static __device__ __forceinline__ void attn_block(Smem* sm, float* xpf,
                                                  int h, int n0, int lane) {
    const int hd0 = h * HDIM;

    float qreg[R], s0[R], s1[R];
    #pragma unroll
    for (int r = 0; r < R; r++) {
        qreg[r] = sm->qs[(n0 + r) * CDIM + hd0 + lane];
        s0[r] = 0.f; s1[r] = 0.f;
    }

    #pragma unroll 8
    for (int d = 0; d < HDIM; d++) {
        float k0 = sm->kt[(hd0 + d) * 51 + lane];
        float k1 = sm->kt[(hd0 + d) * 51 + 32 + lane];   // lanes>=17 read zeroed pad
        #pragma unroll
        for (int r = 0; r < R; r++) {
            float qv = __shfl_sync(FULLM, qreg[r], d);
            s0[r] = fmaf(qv, k0, s0[r]);
            s1[r] = fmaf(qv, k1, s1[r]);
        }
    }

    float uB0 = sm->uBs[lane];
    float uB1 = (lane < 17) ? sm->uBs[lane + 32] : 0.f;
    float p0[R], p1[R];
    #pragma unroll
    for (int r = 0; r < R; r++) {
        int n = n0 + r;
        float bias0 = sm->rtab[sm->ridx[n * NTOK + lane] * 4 + h] - uB0;
        float a0 = fmaf(s0[r], SCALE, bias0);
        float a1 = NEG_INF;
        if (lane < 17) {
            float bias1 = sm->rtab[sm->ridx[n * NTOK + lane + 32] * 4 + h] - uB1;
            a1 = fmaf(s1[r], SCALE, bias1);
        }
        float mx = fmaxf(a0, a1);
        #pragma unroll
        for (int o = 16; o > 0; o >>= 1) mx = fmaxf(mx, __shfl_xor_sync(FULLM, mx, o));
        float e0 = __expf(a0 - mx);
        float e1 = (lane < 17) ? __expf(a1 - mx) : 0.f;
        float smv = e0 + e1;
        #pragma unroll
        for (int o = 16; o > 0; o >>= 1) smv += __shfl_xor_sync(FULLM, smv, o);
        float inv = __fdividef(1.f, smv);
        p0[r] = e0 * inv;
        p1[r] = e1 * inv;
    }

    float o_[R];
    #pragma unroll
    for (int r = 0; r < R; r++) o_[r] = 0.f;
    #pragma unroll 8
    for (int m = 0; m < 32; m++) {
        float vv = sm->vs[m * CDIM + hd0 + lane];
        #pragma unroll
        for (int r = 0; r < R; r++)
            o_[r] = fmaf(__shfl_sync(FULLM, p0[r], m), vv, o_[r]);
    }
    #pragma unroll 8
    for (int m = 0; m < 17; m++) {
        float vv = sm->vs[(m + 32) * CDIM + hd0 + lane];
        #pragma unroll
        for (int r = 0; r < R; r++)
            o_[r] = fmaf(__shfl_sync(FULLM, p1[r], m), vv, o_[r]);
    }

    // gated write into packed xp layout (input to proj GEMM); conflict-free
    const int c = hd0 + lane;
    const int cbase = (c >> 2) * 204 + (c & 3);
    #pragma unroll
    for (int r = 0; r < R; r++) {
        int n = n0 + r;
        xpf[cbase + n * 4] = o_[r] * sm->gts[h * NTOK + n];
    }
}

__global__ void __launch_bounds__(TPB, 1)
attn_win_kernel(const float* __restrict__ x,
                const float* __restrict__ ut,
                const float* __restrict__ ub,
                const float* __restrict__ gate,
                const float* __restrict__ qkv_w,
                const float* __restrict__ qkv_b,
                const float* __restrict__ proj_w,
                const float* __restrict__ proj_b,
                const float* __restrict__ rel_table,
                const int*   __restrict__ rel_index,
                float* __restrict__ out) {
    extern __shared__ char smem_raw[];
    Smem* sm = reinterpret_cast<Smem*>(smem_raw);
    float* xpf = reinterpret_cast<float*>(sm->xp);

    const int b    = blockIdx.x;
    const int tid  = threadIdx.x;
    const int lane = tid & 31;
    const int wy   = tid >> 5;

    // ---------------- stage constants + x ---------------------------
    for (int i = tid; i < NTOK * NTOK; i += TPB) sm->ridx[i] = rel_index[i];
    for (int i = tid; i < 169 * 4; i += TPB)     sm->rtab[i] = rel_table[i];
    for (int i = tid; i < 3 * CDIM; i += TPB)    sm->bqs[i]  = qkv_b[i];
    if (tid < CDIM) sm->pbs[tid] = proj_b[tid];
    if (tid < 64) { sm->invT[tid] = 0.f; sm->uBs[tid] = 0.f; }
    // zero kt pad tail so pad reads in attn are defined
    for (int i = tid; i < 64; i += TPB) sm->kt[CDIM * 51 + i] = 0.f;
    for (int c = 0; c < CDIM; c++) {                 // zero per-row pad [49..50]
        if (tid < 2) sm->kt[c * 51 + 49 + tid] = 0.f;
    }
    __syncthreads();
    if (tid < NTOK) {
        float t  = ut[b * NTOK + tid];
        float sg = 1.f / (1.f + __expf(-t));
        sm->invT[tid] = 1.f / (0.1f + 4.f * sg);
        float u = ub[b * NTOK + tid];
        sm->uBs[tid] = u > 0.f ? u : 0.f;
    }
    if (tid < NHEAD * NTOK) sm->gts[tid] = gate[(size_t)b * (NHEAD * NTOK) + tid];
    #pragma unroll 4
    for (int idx = tid; idx < NTOK * CDIM; idx += TPB) {
        int n = idx >> 7;
        int k = idx & 127;
        xpf[(k >> 2) * 204 + (n << 2) + (k & 3)] = x[(size_t)b * (NTOK * CDIM) + idx];
    }
    stage_w(sm, qkv_w, tid);   // chunk 0 (q)
    __syncthreads();

    // row assignment: warps 0..15 own rows 3*wy..3*wy+2; warp 0 also row 48
    int nrow[4] = {3 * wy, 3 * wy + 1, 3 * wy + 2, 48};
    const bool full4 = (wy == 0);

    // ---------------- qkv GEMM (q, k, v chunks) ----------------------
    unsigned long long acc[4][4];
    for (int j = 0; j < 3; j++) {
        if (full4) gemm_block<4>(sm, nrow, lane, acc);
        else       gemm_block<3>(sm, nrow, lane, acc);
        #pragma unroll
        for (int rr = 0; rr < 4; rr++) {
            if (rr < 3 || full4) {
                int n = nrow[rr];
                #pragma unroll
                for (int cc = 0; cc < 4; cc++) {
                    int c = lane + 32 * cc;
                    float2 s = unpackf2(acc[rr][cc]);
                    float v = s.x + s.y + sm->bqs[j * CDIM + c];
                    if (j == 0)      sm->qs[n * CDIM + c] = v * sm->invT[n];
                    else if (j == 1) sm->kt[c * 51 + n]   = v;
                    else             sm->vs[n * CDIM + c] = v;
                }
            }
        }
        __syncthreads();
        if (j < 2) { stage_w(sm, qkv_w + (j + 1) * 128 * 128, tid); __syncthreads(); }
    }
    // wsp free during attention: stage proj_w now
    stage_w(sm, proj_w, tid);

    // ---------------- attention: 32 blocks = 4 heads x 8 row-groups --
    #pragma unroll
    for (int it = 0; it < 2; it++) {
        int bk = wy + 16 * it;
        int h = bk >> 3, g = bk & 7;
        if (g == 0) attn_block<7>(sm, xpf, h, 0, lane);
        else        attn_block<6>(sm, xpf, h, 6 * g + 1, lane);
    }
    __syncthreads();   // proj_w staged + all xp writes visible

    // ---------------- output projection ------------------------------
    if (full4) gemm_block<4>(sm, nrow, lane, acc);
    else       gemm_block<3>(sm, nrow, lane, acc);
    #pragma unroll
    for (int rr = 0; rr < 4; rr++) {
        if (rr < 3 || full4) {
            int n = nrow[rr];
            #pragma unroll
            for (int cc = 0; cc < 4; cc++) {
                int c = lane + 32 * cc;
                float2 s = unpackf2(acc[rr][cc]);
                out[(size_t)b * (NTOK * CDIM) + n * CDIM + c] = s.x + s.y + sm->pbs[c];
            }
        }
    }
}

extern "C" void kernel_launch(void* const* d_in, const int* in_sizes, int n_in,
                              void* d_out, int out_size) {
    const float* x      = (const float*)d_in[0];
    const float* ut     = (const float*)d_in[1];
    const float* ubias  = (const float*)d_in[2];
    const float* gate   = (const float*)d_in[3];
    const float* qkv_w  = (const float*)d_in[4];
    const float* qkv_b  = (const float*)d_in[5];
    const float* proj_w = (const float*)d_in[6];
    const float* proj_b = (const float*)d_in[7];
    const float* rtab   = (const float*)d_in[8];
    const int*   ridx   = (const int*)d_in[9];
    float* out = (float*)d_out;

    cudaFuncSetAttribute(attn_win_kernel,
                         cudaFuncAttributeMaxDynamicSharedMemorySize, SMEM_BYTES);
    attn_win_kernel<<<B_TOT, TPB, SMEM_BYTES>>>(
        x, ut, ubias, gate, qkv_w, qkv_b, proj_w, proj_b, rtab, ridx, out);
}

// round 7
// speedup vs baseline: 1.5104x; 1.1360x over previous
#include <cuda_runtime.h>
#include <cstdint>

#define B_TOT   4096
#define NTOK    49
#define CDIM    128
#define NHEAD   4
#define HDIM    32
#define TPB     512
#define SCALE   0.17677669529663687f   /* 32^-0.5 */
#define FULLM   0xffffffffu
#define NEG_INF (__int_as_float(0xff800000))

// ---- packed f32x2 helpers (sm_100+ PTX) --------------------------------
static __device__ __forceinline__ void ffma2(unsigned long long& acc,
                                             unsigned long long a,
                                             unsigned long long b) {
    asm("fma.rn.f32x2 %0, %1, %2, %0;" : "+l"(acc) : "l"(a), "l"(b));
}
static __device__ __forceinline__ float2 unpackf2(unsigned long long v) {
    float2 r;
    asm("mov.b64 {%0, %1}, %2;" : "=f"(r.x), "=f"(r.y) : "l"(v));
    return r;
}

// ---- shared memory layout ----------------------------------------------
// wsp: W chunk packed by k-quads: ulonglong2 wsp[k4][col], row pad 129
//      float view: wf[k4*516 + c*4 + (k&3)]
// xp : x (then gated attn output) packed: ulonglong2 xp[k4][n], row pad 51
//      float view: xpf[k4*204 + n*4 + (k&3)]
struct Smem {
    ulonglong2 wsp[32 * 129];              // 66.0 KB
    ulonglong2 xp[32 * 51];                // 26.1 KB
    float qs[NTOK * CDIM];                 // 25.1 KB  q (temp-scaled), row-major
    float kt[CDIM * 51 + 64];              // 26.4 KB  k transposed kt[c*51+m]
    float vs[NTOK * CDIM];                 // 25.1 KB  v row-major
    int   ridx[NTOK * NTOK];               //  9.6 KB
    float rtab[169 * 4];
    float bqs[3 * CDIM];
    float pbs[CDIM];
    float invT[64];
    float uBs[64];
    float gts[NHEAD * NTOK];
};
#define SMEM_BYTES ((int)sizeof(Smem))

// stage a 128x128 weight block W[c][k] -> packed layout; LDG.128 + STS.128
static __device__ __forceinline__ void stage_w(Smem* sm, const float* __restrict__ src, int tid) {
    float* wf = reinterpret_cast<float*>(sm->wsp);
    const float4* s4 = reinterpret_cast<const float4*>(src);
    #pragma unroll
    for (int i = 0; i < 8; i++) {
        int idx = tid + i * TPB;          // idx = c*32 + kq
        int c  = idx >> 5;
        int kq = idx & 31;
        float4 v = s4[idx];
        *reinterpret_cast<float4*>(wf + kq * 516 + c * 4) = v;
    }
}

// NR rows x 64 cols GEMM (col-half cg): acc[rr][cc] packed (lo=even k, hi=odd k)
template <int NR>
static __device__ __forceinline__ void gemm_block(const Smem* sm, int n0, int cg,
                                                  int lane, unsigned long long (&acc)[7][2]) {
    #pragma unroll
    for (int rr = 0; rr < NR; rr++) { acc[rr][0] = 0ull; acc[rr][1] = 0ull; }

    const ulonglong2* wq = sm->wsp;
    const ulonglong2* xq = sm->xp;
    const int wbase = cg * 64 + lane;
    #pragma unroll 4
    for (int k4 = 0; k4 < 32; k4++) {
        ulonglong2 w0 = wq[k4 * 129 + wbase];
        ulonglong2 w1 = wq[k4 * 129 + wbase + 32];
        ulonglong2 xv[NR];
        #pragma unroll
        for (int rr = 0; rr < NR; rr++) xv[rr] = xq[k4 * 51 + n0 + rr];  // broadcast
        #pragma unroll
        for (int rr = 0; rr < NR; rr++) {
            ffma2(acc[rr][0], xv[rr].x, w0.x);
            ffma2(acc[rr][1], xv[rr].x, w1.x);
        }
        #pragma unroll
        for (int rr = 0; rr < NR; rr++) {
            ffma2(acc[rr][0], xv[rr].y, w0.y);
            ffma2(acc[rr][1], xv[rr].y, w1.y);
        }
    }
}

// attention for one (head, row-group) block; R rows, warp lanes = keys / dims
template <int R>
static __device__ __forceinline__ void attn_block(Smem* sm, float* xpf,
                                                  int h, int n0, int lane) {
    const int hd0 = h * HDIM;

    float qreg[R], s0[R], s1[R];
    #pragma unroll
    for (int r = 0; r < R; r++) {
        qreg[r] = sm->qs[(n0 + r) * CDIM + hd0 + lane];
        s0[r] = 0.f; s1[r] = 0.f;
    }

    #pragma unroll 8
    for (int d = 0; d < HDIM; d++) {
        float k0 = sm->kt[(hd0 + d) * 51 + lane];
        float k1 = sm->kt[(hd0 + d) * 51 + 32 + lane];   // lanes>=17: dead values
        #pragma unroll
        for (int r = 0; r < R; r++) {
            float qv = __shfl_sync(FULLM, qreg[r], d);
            s0[r] = fmaf(qv, k0, s0[r]);
            s1[r] = fmaf(qv, k1, s1[r]);
        }
    }

    float uB0 = sm->uBs[lane];
    float uB1 = (lane < 17) ? sm->uBs[lane + 32] : 0.f;
    float p0[R], p1[R];
    #pragma unroll
    for (int r = 0; r < R; r++) {
        int n = n0 + r;
        float bias0 = sm->rtab[sm->ridx[n * NTOK + lane] * 4 + h] - uB0;
        float a0 = fmaf(s0[r], SCALE, bias0);
        float a1 = NEG_INF;
        if (lane < 17) {
            float bias1 = sm->rtab[sm->ridx[n * NTOK + lane + 32] * 4 + h] - uB1;
            a1 = fmaf(s1[r], SCALE, bias1);
        }
        float mx = fmaxf(a0, a1);
        #pragma unroll
        for (int o = 16; o > 0; o >>= 1) mx = fmaxf(mx, __shfl_xor_sync(FULLM, mx, o));
        float e0 = __expf(a0 - mx);
        float e1 = (lane < 17) ? __expf(a1 - mx) : 0.f;
        float smv = e0 + e1;
        #pragma unroll
        for (int o = 16; o > 0; o >>= 1) smv += __shfl_xor_sync(FULLM, smv, o);
        float inv = __fdividef(1.f, smv);
        p0[r] = e0 * inv;
        p1[r] = e1 * inv;
    }

    float o_[R];
    #pragma unroll
    for (int r = 0; r < R; r++) o_[r] = 0.f;
    #pragma unroll 8
    for (int m = 0; m < 32; m++) {
        float vv = sm->vs[m * CDIM + hd0 + lane];
        #pragma unroll
        for (int r = 0; r < R; r++)
            o_[r] = fmaf(__shfl_sync(FULLM, p0[r], m), vv, o_[r]);
    }
    #pragma unroll 8
    for (int m = 0; m < 17; m++) {
        float vv = sm->vs[(m + 32) * CDIM + hd0 + lane];
        #pragma unroll
        for (int r = 0; r < R; r++)
            o_[r] = fmaf(__shfl_sync(FULLM, p1[r], m), vv, o_[r]);
    }

    // gated write into packed xp layout (input to proj GEMM); conflict-free
    const int c = hd0 + lane;
    const int cbase = (c >> 2) * 204 + (c & 3);
    #pragma unroll
    for (int r = 0; r < R; r++) {
        int n = n0 + r;
        xpf[cbase + n * 4] = o_[r] * sm->gts[h * NTOK + n];
    }
}

__global__ void __launch_bounds__(TPB, 1)
attn_win_kernel(const float* __restrict__ x,
                const float* __restrict__ ut,
                const float* __restrict__ ub,
                const float* __restrict__ gate,
                const float* __restrict__ qkv_w,
                const float* __restrict__ qkv_b,
                const float* __restrict__ proj_w,
                const float* __restrict__ proj_b,
                const float* __restrict__ rel_table,
                const int*   __restrict__ rel_index,
                float* __restrict__ out) {
    extern __shared__ char smem_raw[];
    Smem* sm = reinterpret_cast<Smem*>(smem_raw);
    float* xpf = reinterpret_cast<float*>(sm->xp);

    const int b    = blockIdx.x;
    const int tid  = threadIdx.x;
    const int lane = tid & 31;
    const int wy   = tid >> 5;

    // ---------------- stage constants + x ---------------------------
    for (int i = tid; i < NTOK * NTOK; i += TPB) sm->ridx[i] = rel_index[i];
    for (int i = tid; i < 169 * 4; i += TPB)     sm->rtab[i] = rel_table[i];
    for (int i = tid; i < 3 * CDIM; i += TPB)    sm->bqs[i]  = qkv_b[i];
    if (tid < CDIM) sm->pbs[tid] = proj_b[tid];
    if (tid < 64) { sm->invT[tid] = 0.f; sm->uBs[tid] = 0.f; }
    // zero kt pads (per-row pad rows 49..50 and tail) so attn pad reads are defined
    for (int idx = tid; idx < 256; idx += TPB) {
        int c = idx >> 1, p = idx & 1;
        sm->kt[c * 51 + 49 + p] = 0.f;
    }
    if (tid < 64) sm->kt[CDIM * 51 + tid] = 0.f;
    __syncthreads();
    if (tid < NTOK) {
        float t  = ut[b * NTOK + tid];
        float sg = 1.f / (1.f + __expf(-t));
        sm->invT[tid] = 1.f / (0.1f + 4.f * sg);
        float u = ub[b * NTOK + tid];
        sm->uBs[tid] = u > 0.f ? u : 0.f;
    }
    if (tid < NHEAD * NTOK) sm->gts[tid] = gate[(size_t)b * (NHEAD * NTOK) + tid];
    {   // x: float4 per (n, k-quad): LDG.128 + STS.128, packed layout
        const float4* x4 = reinterpret_cast<const float4*>(x + (size_t)b * (NTOK * CDIM));
        #pragma unroll
        for (int i = 0; i < 4; i++) {
            int idx = tid + i * TPB;       // idx = n*32 + kq
            if (idx < NTOK * 32) {
                int n = idx >> 5, kq = idx & 31;
                float4 v = x4[idx];
                *reinterpret_cast<float4*>(xpf + kq * 204 + n * 4) = v;
            }
        }
    }
    stage_w(sm, qkv_w, tid);   // chunk 0 (q)
    __syncthreads();

    // warp partition: 8 row-groups x 2 col-halves
    const int rg = wy >> 1, cg = wy & 1;
    const int n0 = (rg == 0) ? 0 : 6 * rg + 1;
    const int NRv = (rg == 0) ? 7 : 6;

    // ---------------- qkv GEMM (q, k, v chunks) ----------------------
    unsigned long long acc[7][2];
    for (int j = 0; j < 3; j++) {
        if (rg == 0) gemm_block<7>(sm, n0, cg, lane, acc);
        else         gemm_block<6>(sm, n0, cg, lane, acc);
        #pragma unroll
        for (int rr = 0; rr < 7; rr++) {
            if (rr < NRv) {
                int n = n0 + rr;
                #pragma unroll
                for (int cc = 0; cc < 2; cc++) {
                    int c = cg * 64 + 32 * cc + lane;
                    float2 s = unpackf2(acc[rr][cc]);
                    float v = s.x + s.y + sm->bqs[j * CDIM + c];
                    if (j == 0)      sm->qs[n * CDIM + c] = v * sm->invT[n];
                    else if (j == 1) sm->kt[c * 51 + n]   = v;
                    else             sm->vs[n * CDIM + c] = v;
                }
            }
        }
        __syncthreads();
        if (j < 2) { stage_w(sm, qkv_w + (j + 1) * 128 * 128, tid); __syncthreads(); }
    }
    // wsp free during attention: stage proj_w now
    stage_w(sm, proj_w, tid);

    // ---------------- attention: 32 blocks = 4 heads x 8 row-groups --
    #pragma unroll
    for (int it = 0; it < 2; it++) {
        int bk = wy + 16 * it;
        int h = bk >> 3, g = bk & 7;
        if (g == 0) attn_block<7>(sm, xpf, h, 0, lane);
        else        attn_block<6>(sm, xpf, h, 6 * g + 1, lane);
    }
    __syncthreads();   // proj_w staged + all xp writes visible

    // ---------------- output projection ------------------------------
    if (rg == 0) gemm_block<7>(sm, n0, cg, lane, acc);
    else         gemm_block<6>(sm, n0, cg, lane, acc);
    #pragma unroll
    for (int rr = 0; rr < 7; rr++) {
        if (rr < NRv) {
            int n = n0 + rr;
            #pragma unroll
            for (int cc = 0; cc < 2; cc++) {
                int c = cg * 64 + 32 * cc + lane;
                float2 s = unpackf2(acc[rr][cc]);
                out[(size_t)b * (NTOK * CDIM) + n * CDIM + c] = s.x + s.y + sm->pbs[c];
            }
        }
    }
}

extern "C" void kernel_launch(void* const* d_in, const int* in_sizes, int n_in,
                              void* d_out, int out_size) {
    const float* x      = (const float*)d_in[0];
    const float* ut     = (const float*)d_in[1];
    const float* ubias  = (const float*)d_in[2];
    const float* gate   = (const float*)d_in[3];
    const float* qkv_w  = (const float*)d_in[4];
    const float* qkv_b  = (const float*)d_in[5];
    const float* proj_w = (const float*)d_in[6];
    const float* proj_b = (const float*)d_in[7];
    const float* rtab   = (const float*)d_in[8];
    const int*   ridx   = (const int*)d_in[9];
    float* out = (float*)d_out;

    cudaFuncSetAttribute(attn_win_kernel,
                         cudaFuncAttributeMaxDynamicSharedMemorySize, SMEM_BYTES);
    attn_win_kernel<<<B_TOT, TPB, SMEM_BYTES>>>(
        x, ut, ubias, gate, qkv_w, qkv_b, proj_w, proj_b, rtab, ridx, out);
}

// round 8
// speedup vs baseline: 1.5848x; 1.0493x over previous
#include <cuda_runtime.h>
#include <cstdint>

#define B_TOT   4096
#define NTOK    49
#define CDIM    128
#define NHEAD   4
#define HDIM    32
#define TPB     512
#define SCALE   0.17677669529663687f   /* 32^-0.5 */
#define FULLM   0xffffffffu
#define NEG_INF (__int_as_float(0xff800000))

typedef unsigned long long u64;

// ---- packed f32x2 helpers (sm_100+ PTX) --------------------------------
static __device__ __forceinline__ void ffma2(u64& acc, u64 a, u64 b) {
    asm("fma.rn.f32x2 %0, %1, %2, %0;" : "+l"(acc) : "l"(a), "l"(b));
}
static __device__ __forceinline__ float2 unpackf2(u64 v) {
    float2 r;
    asm("mov.b64 {%0, %1}, %2;" : "=f"(r.x), "=f"(r.y) : "l"(v));
    return r;
}

// ---- shared memory layout ----------------------------------------------
// wsp: W chunk packed by k-quads: ulonglong2 wsp[k4][col], row pad 129
// xp : x (then gated attn output) packed by k-quads: xp[k4][n], row pad 51
// qp/ktp: q,k packed by d-PAIRS: u64 (v[n][2d],v[n][2d+1]) at [d2*51 + n]
// vp : v packed by m-PAIRS: u64 (v[2m2][c],v[2m2+1][c]) at [m2*130 + c]
// pp : per-warp prob rows: pp[wy*364 + r*52 + m]  (m pad 49..51 zeroed)
struct Smem {
    ulonglong2 wsp[32 * 129];              // 66.0 KB
    ulonglong2 xp[32 * 51];                // 26.1 KB
    u64  qp[64 * 51];                      // 26.1 KB
    u64  ktp[64 * 51];                     // 26.1 KB
    u64  vp[25 * 130];                     // 26.0 KB
    float pp[16 * 7 * 52];                 // 23.3 KB
    int   ridx[NTOK * NTOK];               //  9.6 KB
    float rtab[169 * 4];
    float bqs[3 * CDIM];
    float pbs[CDIM];
    float invT[64];
    float uBs[64];
    float gts[NHEAD * NTOK];
};
#define SMEM_BYTES ((int)sizeof(Smem))

// stage a 128x128 weight block W[c][k] -> packed layout; LDG.128 + STS.128
static __device__ __forceinline__ void stage_w(Smem* sm, const float* __restrict__ src, int tid) {
    float* wf = reinterpret_cast<float*>(sm->wsp);
    const float4* s4 = reinterpret_cast<const float4*>(src);
    #pragma unroll
    for (int i = 0; i < 8; i++) {
        int idx = tid + i * TPB;          // idx = c*32 + kq
        int c  = idx >> 5;
        int kq = idx & 31;
        float4 v = s4[idx];
        *reinterpret_cast<float4*>(wf + kq * 516 + c * 4) = v;
    }
}

// NR rows x 64 cols GEMM (col-half cg): acc[rr][cc] packed (lo=even k, hi=odd k)
template <int NR>
static __device__ __forceinline__ void gemm_block(const Smem* sm, int n0, int cg,
                                                  int lane, u64 (&acc)[7][2]) {
    #pragma unroll
    for (int rr = 0; rr < NR; rr++) { acc[rr][0] = 0ull; acc[rr][1] = 0ull; }

    const ulonglong2* wq = sm->wsp;
    const ulonglong2* xq = sm->xp;
    const int wbase = cg * 64 + lane;
    #pragma unroll 4
    for (int k4 = 0; k4 < 32; k4++) {
        ulonglong2 w0 = wq[k4 * 129 + wbase];
        ulonglong2 w1 = wq[k4 * 129 + wbase + 32];
        ulonglong2 xv[NR];
        #pragma unroll
        for (int rr = 0; rr < NR; rr++) xv[rr] = xq[k4 * 51 + n0 + rr];  // broadcast
        #pragma unroll
        for (int rr = 0; rr < NR; rr++) {
            ffma2(acc[rr][0], xv[rr].x, w0.x);
            ffma2(acc[rr][1], xv[rr].x, w1.x);
        }
        #pragma unroll
        for (int rr = 0; rr < NR; rr++) {
            ffma2(acc[rr][0], xv[rr].y, w0.y);
            ffma2(acc[rr][1], xv[rr].y, w1.y);
        }
    }
}

// attention for one (head, row-group) block; R rows, lanes = keys (QK) / dims (PV)
template <int R>
static __device__ __forceinline__ void attn_block(Smem* sm, float* xpf,
                                                  int h, int n0, int lane, int wy) {
    const int h16 = h * 16;        // d2 base for this head
    const int hd0 = h * HDIM;      // channel base
    const u64* ktu = sm->ktp;
    const u64* qpu = sm->qp;
    const u64* vpu = sm->vp;
    float* ppw = sm->pp + wy * 364;

    // ---- QK: packed over d-pairs, broadcast q ----
    u64 s0[R], s1[R];
    #pragma unroll
    for (int r = 0; r < R; r++) { s0[r] = 0ull; s1[r] = 0ull; }
    #pragma unroll 8
    for (int dd = 0; dd < 16; dd++) {
        u64 k0 = ktu[(h16 + dd) * 51 + lane];
        u64 k1 = ktu[(h16 + dd) * 51 + 32 + lane];   // lanes>=17: dead (guarded below)
        #pragma unroll
        for (int r = 0; r < R; r++) {
            u64 qv = qpu[(h16 + dd) * 51 + n0 + r];  // 8B broadcast
            ffma2(s0[r], qv, k0);
            ffma2(s1[r], qv, k1);
        }
    }

    // ---- softmax (lanes = keys) ----
    float uB0 = sm->uBs[lane];
    float uB1 = (lane < 17) ? sm->uBs[lane + 32] : 0.f;
    #pragma unroll
    for (int r = 0; r < R; r++) {
        int n = n0 + r;
        float2 t0 = unpackf2(s0[r]);
        float2 t1 = unpackf2(s1[r]);
        float sc0 = t0.x + t0.y;
        float sc1 = t1.x + t1.y;
        float bias0 = sm->rtab[sm->ridx[n * NTOK + lane] * 4 + h] - uB0;
        float a0 = fmaf(sc0, SCALE, bias0);
        float a1 = NEG_INF;
        if (lane < 17) {
            float bias1 = sm->rtab[sm->ridx[n * NTOK + lane + 32] * 4 + h] - uB1;
            a1 = fmaf(sc1, SCALE, bias1);
        }
        float mx = fmaxf(a0, a1);
        #pragma unroll
        for (int o = 16; o > 0; o >>= 1) mx = fmaxf(mx, __shfl_xor_sync(FULLM, mx, o));
        float e0 = __expf(a0 - mx);
        float e1 = (lane < 17) ? __expf(a1 - mx) : 0.f;
        float smv = e0 + e1;
        #pragma unroll
        for (int o = 16; o > 0; o >>= 1) smv += __shfl_xor_sync(FULLM, smv, o);
        float inv = __fdividef(1.f, smv);
        ppw[r * 52 + lane] = e0 * inv;
        if (lane < 17) ppw[r * 52 + 32 + lane] = e1 * inv;
    }
    __syncwarp();

    // ---- PV: packed over m-pairs, broadcast probs; lanes = head dims ----
    const u64* ppu = reinterpret_cast<const u64*>(ppw);  // [r*26 + m2]
    u64 o2[R];
    #pragma unroll
    for (int r = 0; r < R; r++) o2[r] = 0ull;
    #pragma unroll 5
    for (int m2 = 0; m2 < 25; m2++) {
        u64 vv = vpu[m2 * 130 + hd0 + lane];
        #pragma unroll
        for (int r = 0; r < R; r++) {
            u64 pv = ppu[r * 26 + m2];               // 8B broadcast
            ffma2(o2[r], pv, vv);
        }
    }

    // gated write into packed xp layout (input to proj GEMM); conflict-free
    const int c = hd0 + lane;
    const int cbase = (c >> 2) * 204 + (c & 3);
    #pragma unroll
    for (int r = 0; r < R; r++) {
        int n = n0 + r;
        float2 t = unpackf2(o2[r]);
        xpf[cbase + n * 4] = (t.x + t.y) * sm->gts[h * NTOK + n];
    }
    __syncwarp();   // pp reads done before next block overwrites
}

__global__ void __launch_bounds__(TPB, 1)
attn_win_kernel(const float* __restrict__ x,
                const float* __restrict__ ut,
                const float* __restrict__ ub,
                const float* __restrict__ gate,
                const float* __restrict__ qkv_w,
                const float* __restrict__ qkv_b,
                const float* __restrict__ proj_w,
                const float* __restrict__ proj_b,
                const float* __restrict__ rel_table,
                const int*   __restrict__ rel_index,
                float* __restrict__ out) {
    extern __shared__ char smem_raw[];
    Smem* sm = reinterpret_cast<Smem*>(smem_raw);
    float* xpf  = reinterpret_cast<float*>(sm->xp);
    float* qpf  = reinterpret_cast<float*>(sm->qp);
    float* ktpf = reinterpret_cast<float*>(sm->ktp);
    float* vpf  = reinterpret_cast<float*>(sm->vp);

    const int b    = blockIdx.x;
    const int tid  = threadIdx.x;
    const int lane = tid & 31;
    const int wy   = tid >> 5;

    // ---------------- stage constants + x + zero pads ----------------
    for (int i = tid; i < NTOK * NTOK; i += TPB) sm->ridx[i] = rel_index[i];
    for (int i = tid; i < 169 * 4; i += TPB)     sm->rtab[i] = rel_table[i];
    for (int i = tid; i < 3 * CDIM; i += TPB)    sm->bqs[i]  = qkv_b[i];
    if (tid < CDIM) sm->pbs[tid] = proj_b[tid];
    // zero pp (covers prob pads m=49..51)
    for (int i = tid; i < 16 * 7 * 52; i += TPB) sm->pp[i] = 0.f;
    // zero ktp pads (m = 49,50 of every d2 row)
    if (tid < 256) {
        int d2 = tid >> 2, off = tid & 3;
        ktpf[d2 * 102 + 98 + off] = 0.f;
    }
    // zero vp pad row m=49 (hi half of m2=24)
    if (tid < 128) vpf[24 * 260 + 2 * tid + 1] = 0.f;
    if (tid < NTOK) {
        float t  = ut[b * NTOK + tid];
        float sg = 1.f / (1.f + __expf(-t));
        sm->invT[tid] = 1.f / (0.1f + 4.f * sg);
        float u = ub[b * NTOK + tid];
        sm->uBs[tid] = u > 0.f ? u : 0.f;
    }
    if (tid < NHEAD * NTOK) sm->gts[tid] = gate[(size_t)b * (NHEAD * NTOK) + tid];
    {   // x: float4 per (n, k-quad): LDG.128 + STS.128, packed layout
        const float4* x4 = reinterpret_cast<const float4*>(x + (size_t)b * (NTOK * CDIM));
        #pragma unroll
        for (int i = 0; i < 4; i++) {
            int idx = tid + i * TPB;       // idx = n*32 + kq
            if (idx < NTOK * 32) {
                int n = idx >> 5, kq = idx & 31;
                float4 v = x4[idx];
                *reinterpret_cast<float4*>(xpf + kq * 204 + n * 4) = v;
            }
        }
    }
    stage_w(sm, qkv_w, tid);   // chunk 0 (q)
    __syncthreads();

    // warp partition: 8 row-groups x 2 col-halves
    const int rg = wy >> 1, cg = wy & 1;
    const int n0 = (rg == 0) ? 0 : 6 * rg + 1;
    const int NRv = (rg == 0) ? 7 : 6;

    // ---------------- qkv GEMM (q, k, v chunks) ----------------------
    u64 acc[7][2];
    for (int j = 0; j < 3; j++) {
        if (rg == 0) gemm_block<7>(sm, n0, cg, lane, acc);
        else         gemm_block<6>(sm, n0, cg, lane, acc);
        #pragma unroll
        for (int rr = 0; rr < 7; rr++) {
            if (rr < NRv) {
                int n = n0 + rr;
                #pragma unroll
                for (int cc = 0; cc < 2; cc++) {
                    int c = cg * 64 + 32 * cc + lane;
                    float2 s = unpackf2(acc[rr][cc]);
                    float v = s.x + s.y + sm->bqs[j * CDIM + c];
                    if (j == 0)      qpf[(c >> 1) * 102 + n * 2 + (c & 1)] = v * sm->invT[n];
                    else if (j == 1) ktpf[(c >> 1) * 102 + n * 2 + (c & 1)] = v;
                    else             vpf[(n >> 1) * 260 + (c << 1) + (n & 1)] = v;
                }
            }
        }
        __syncthreads();
        if (j < 2) { stage_w(sm, qkv_w + (j + 1) * 128 * 128, tid); __syncthreads(); }
    }
    // wsp free during attention: stage proj_w now
    stage_w(sm, proj_w, tid);

    // ---------------- attention: 32 blocks = 4 heads x 8 row-groups --
    #pragma unroll
    for (int it = 0; it < 2; it++) {
        int bk = wy + 16 * it;
        int h = bk >> 3, g = bk & 7;
        if (g == 0) attn_block<7>(sm, xpf, h, 0, lane, wy);
        else        attn_block<6>(sm, xpf, h, 6 * g + 1, lane, wy);
    }
    __syncthreads();   // proj_w staged + all xp writes visible

    // ---------------- output projection ------------------------------
    if (rg == 0) gemm_block<7>(sm, n0, cg, lane, acc);
    else         gemm_block<6>(sm, n0, cg, lane, acc);
    #pragma unroll
    for (int rr = 0; rr < 7; rr++) {
        if (rr < NRv) {
            int n = n0 + rr;
            #pragma unroll
            for (int cc = 0; cc < 2; cc++) {
                int c = cg * 64 + 32 * cc + lane;
                float2 s = unpackf2(acc[rr][cc]);
                out[(size_t)b * (NTOK * CDIM) + n * CDIM + c] = s.x + s.y + sm->pbs[c];
            }
        }
    }
}

extern "C" void kernel_launch(void* const* d_in, const int* in_sizes, int n_in,
                              void* d_out, int out_size) {
    const float* x      = (const float*)d_in[0];
    const float* ut     = (const float*)d_in[1];
    const float* ubias  = (const float*)d_in[2];
    const float* gate   = (const float*)d_in[3];
    const float* qkv_w  = (const float*)d_in[4];
    const float* qkv_b  = (const float*)d_in[5];
    const float* proj_w = (const float*)d_in[6];
    const float* proj_b = (const float*)d_in[7];
    const float* rtab   = (const float*)d_in[8];
    const int*   ridx   = (const int*)d_in[9];
    float* out = (float*)d_out;

    cudaFuncSetAttribute(attn_win_kernel,
                         cudaFuncAttributeMaxDynamicSharedMemorySize, SMEM_BYTES);
    attn_win_kernel<<<B_TOT, TPB, SMEM_BYTES>>>(
        x, ut, ubias, gate, qkv_w, qkv_b, proj_w, proj_b, rtab, ridx, out);
}